// round 8
// baseline (speedup 1.0000x reference)
#include <cuda_runtime.h>

#define NH 8
#define DD 1024
#define MM 2048
#define PIX4 12288      // 128*128*3 / 4
#define MSLICE 128      // m per wsum tile
#define XT 48           // x-tiles (PIX4 / 256)
#define NTILES (XT * (MM / MSLICE))   // 48*16 = 768
#define PGRID 444       // 148 SMs x 3 blocks, all-resident persistent
#define NWARPS (PGRID*8)

__device__ float g_q[NH*DD];
__device__ float g_t[NH*DD];
__device__ float g_c[NH];
__device__ float g_sums[NH];
__device__ float g_wt[MM*NH];   // unnormalized exp weights, transposed [m][h]
__device__ int   g_ctr;         // wsum ticket counter (reset by prep)
__device__ int   g_bar;         // prep grid barrier  (reset by wsum)

__device__ __forceinline__ unsigned long long pk2(float a, float b){
    unsigned long long r;
    asm("mov.b64 %0, {%1, %2};" : "=l"(r) : "f"(a), "f"(b));
    return r;
}
__device__ __forceinline__ void fma2(unsigned long long &acc, unsigned long long v, unsigned long long w){
    asm("fma.rn.f32x2 %0, %1, %2, %0;" : "+l"(acc) : "l"(v), "l"(w));
}
__device__ __forceinline__ void upk2(unsigned long long p, float &a, float &b){
    asm("mov.b64 {%0, %1}, %2;" : "=f"(a), "=f"(b) : "l"(p));
}

// Grid barrier: all PGRID blocks resident by construction (444 <= 152*3).
__device__ __forceinline__ void grid_bar(int target) {
    __syncthreads();
    __threadfence();
    if (threadIdx.x == 0) {
        atomicAdd(&g_bar, 1);
        while (*(volatile int*)&g_bar < target) __nanosleep(64);
    }
    __syncthreads();
    __threadfence();   // acquire: subsequent loads see other blocks' writes
}

// ---------------------------------------------------------------------------
// Fused prologue: one persistent kernel, 3 phases, 2 grid barriers.
//   A: zero g_t/g_c/g_sums; q[h,e] = Q.WQ[h,e,:] + bQ  (warp tasks)
//   B: t[h,d] += q[h,e]*WK[h,e,d] (REDG);  c[h] = q[h].bK[h]
//   C: g_wt[m][h] = exp((K[m].t[h] + c[h])/1024); sums; zero d_out; g_ctr=0
// ---------------------------------------------------------------------------
__global__ void __launch_bounds__(256, 3) prep_kernel(
        const float* __restrict__ Q,  const float* __restrict__ K,
        const float* __restrict__ WQ, const float* __restrict__ bQ,
        const float* __restrict__ WK, const float* __restrict__ bK,
        float4* __restrict__ out4) {
    __shared__ float4 ts4[NH*DD/4];   // 32 KB (phase C)
    __shared__ float ws[8][NH];
    int tid  = threadIdx.x;
    int gid  = blockIdx.x*256 + tid;
    int lane = tid & 31;
    int gwarp = gid >> 5;

    // ---- Phase A ----
    if (gid == 0) g_ctr = 0;                   // reset wsum tickets for this replay
    if (gid < NH*DD) g_t[gid] = 0.f;
    if (gid < NH) { g_c[gid] = 0.f; g_sums[gid] = 0.f; }

    const float4* Q4 = (const float4*)Q;
    for (int task = gwarp; task < NH*DD; task += NWARPS) {
        int h = task >> 10, e = task & 1023;
        const float4* W4 = (const float4*)WQ + (size_t)h*(DD*DD/4) + (size_t)e*(DD/4);
        float acc = 0.f;
        #pragma unroll
        for (int i = 0; i < 8; i++) {
            float4 w = __ldcs(&W4[lane + i*32]);
            float4 q = Q4[lane + i*32];
            acc += w.x*q.x + w.y*q.y + w.z*q.z + w.w*q.w;
        }
        #pragma unroll
        for (int o = 16; o; o >>= 1) acc += __shfl_xor_sync(0xffffffffu, acc, o);
        if (lane == 0) g_q[h*DD + e] = acc + bQ[h*DD + e];
    }
    grid_bar(PGRID);

    // ---- Phase B ---- (1024 block-tasks: (h, e-chunk of 8))
    for (int t = blockIdx.x; t < 1024; t += PGRID) {
        int h = t >> 7, e0 = (t & 127) * 8;
        const float4* Wp = (const float4*)(WK + (size_t)h*DD*DD + (size_t)e0*DD) + tid;
        const float* qp = g_q + h*DD + e0;
        float4 acc = make_float4(0.f, 0.f, 0.f, 0.f);
        #pragma unroll
        for (int e = 0; e < 8; e++) {
            float qe = __ldcg(&qp[e]);
            float4 w = __ldcs(&Wp[(size_t)e*(DD/4)]);
            acc.x = fmaf(qe, w.x, acc.x);
            acc.y = fmaf(qe, w.y, acc.y);
            acc.z = fmaf(qe, w.z, acc.z);
            acc.w = fmaf(qe, w.w, acc.w);
        }
        float* p = &g_t[h*DD + tid*4];
        asm volatile("red.global.add.v4.f32 [%0], {%1, %2, %3, %4};"
                     :: "l"(p), "f"(acc.x), "f"(acc.y), "f"(acc.z), "f"(acc.w) : "memory");
    }
    if (blockIdx.x < 64 && tid < 32) {          // c[h] = q[h] . bK[h]
        int h = blockIdx.x >> 3, e0 = (blockIdx.x & 7) * 128;
        float v = 0.f;
        #pragma unroll
        for (int j = 0; j < 4; j++) {
            int e = e0 + lane + j*32;
            v = fmaf(__ldcg(&g_q[h*DD + e]), bK[h*DD + e], v);
        }
        #pragma unroll
        for (int o = 16; o; o >>= 1) v += __shfl_xor_sync(0xffffffffu, v, o);
        if (lane == 0) atomicAdd(&g_c[h], v);
    }
    grid_bar(2*PGRID);

    // ---- Phase C ----
    for (int idx = gid; idx < NH*PIX4; idx += PGRID*256)
        out4[idx] = make_float4(0.f, 0.f, 0.f, 0.f);

    if (blockIdx.x < 256) {
        for (int i = tid; i < NH*DD/4; i += 256) {
            const float* s = &g_t[i*4];
            ts4[i] = make_float4(__ldcg(s), __ldcg(s+1), __ldcg(s+2), __ldcg(s+3));
        }
        __syncthreads();

        int wid = tid >> 5;
        int m = blockIdx.x * 8 + wid;
        const float4* K4 = (const float4*)K + (size_t)m*(DD/4);
        float acc[NH];
        #pragma unroll
        for (int h = 0; h < NH; h++) acc[h] = 0.f;
        #pragma unroll
        for (int i = 0; i < 8; i++) {
            float4 k4 = K4[lane + i*32];
            #pragma unroll
            for (int h = 0; h < NH; h++) {
                float4 t4 = ts4[h*256 + lane + i*32];
                acc[h] += k4.x*t4.x + k4.y*t4.y + k4.z*t4.z + k4.w*t4.w;
            }
        }
        #pragma unroll
        for (int h = 0; h < NH; h++) {
            #pragma unroll
            for (int o = 16; o; o >>= 1) acc[h] += __shfl_xor_sync(0xffffffffu, acc[h], o);
        }
        if (lane == 0) {
            #pragma unroll
            for (int h = 0; h < NH; h++) {
                float w = expf((acc[h] + __ldcg(&g_c[h])) * (1.0f/1024.0f));
                g_wt[m*NH + h] = w;
                ws[wid][h] = w;
            }
        }
        __syncthreads();
        if (tid < NH) {
            float s = 0.f;
            #pragma unroll
            for (int w8 = 0; w8 < 8; w8++) s += ws[w8][tid];
            atomicAdd(&g_sums[tid], s);
        }
    }
}

// ---------------------------------------------------------------------------
// wsum: persistent ticket-scheduled weighted V sum, MSLICE=128.
//   out[h][:] += sum_m (w[h,m]/sum[h]) * V[m,:]
// ---------------------------------------------------------------------------
__device__ __forceinline__ void accum4(const float4 v[4],
                                       const unsigned long long* __restrict__ w2s,
                                       int lm,
                                       unsigned long long a0[NH],
                                       unsigned long long a1[NH]) {
    #pragma unroll
    for (int u = 0; u < 4; u++) {
        unsigned long long v01 = pk2(v[u].x, v[u].y);
        unsigned long long v23 = pk2(v[u].z, v[u].w);
        const ulonglong2* wr = (const ulonglong2*)&w2s[(lm + u)*NH];
        #pragma unroll
        for (int h2 = 0; h2 < 4; h2++) {
            ulonglong2 wp = wr[h2];
            fma2(a0[2*h2],   v01, wp.x);
            fma2(a1[2*h2],   v23, wp.x);
            fma2(a0[2*h2+1], v01, wp.y);
            fma2(a1[2*h2+1], v23, wp.y);
        }
    }
}

__global__ void __launch_bounds__(256, 3) wsum_kernel(const float* __restrict__ V,
                                                      float4* __restrict__ out4) {
    __shared__ unsigned long long w2s[MSLICE*NH];   // 8 KB, normalized (w,w)
    __shared__ int s_tile;
    int tid = threadIdx.x;
    if (blockIdx.x == 0 && tid == 0) g_bar = 0;     // reset prep barrier for next replay

    for (;;) {
        if (tid == 0) s_tile = atomicAdd(&g_ctr, 1);
        __syncthreads();                 // publishes ticket; fences prev w2s reads
        int t = s_tile;
        if (t >= NTILES) break;
        int s  = t / XT;
        int xb = t - s*XT;
        int m0 = s * MSLICE;

        for (int i = tid; i < MSLICE*NH; i += 256) {
            float w = __fdividef(g_wt[m0*NH + i], g_sums[i & 7]);
            w2s[i] = pk2(w, w);
        }
        __syncthreads();

        int jj = xb*256 + tid;
        const float4* V4 = (const float4*)V + (size_t)m0*PIX4 + jj;
        unsigned long long a0[NH], a1[NH];
        #pragma unroll
        for (int h = 0; h < NH; h++) { a0[h] = 0ull; a1[h] = 0ull; }

        float4 va[4], vb[4];
        #pragma unroll
        for (int u = 0; u < 4; u++) va[u] = __ldcs(&V4[(size_t)u * PIX4]);

        #pragma unroll 1
        for (int lm = 0; lm < MSLICE; lm += 8) {
            #pragma unroll
            for (int u = 0; u < 4; u++)
                vb[u] = __ldcs(&V4[(size_t)(lm + 4 + u) * PIX4]);
            accum4(va, w2s, lm, a0, a1);
            if (lm + 8 < MSLICE) {
                #pragma unroll
                for (int u = 0; u < 4; u++)
                    va[u] = __ldcs(&V4[(size_t)(lm + 8 + u) * PIX4]);
            }
            accum4(vb, w2s, lm + 4, a0, a1);
        }

        #pragma unroll
        for (int h = 0; h < NH; h++) {
            float x, y, z, w;
            upk2(a0[h], x, y);
            upk2(a1[h], z, w);
            float* p = (float*)&out4[h*PIX4 + jj];
            asm volatile("red.global.add.v4.f32 [%0], {%1, %2, %3, %4};"
                         :: "l"(p), "f"(x), "f"(y), "f"(z), "f"(w) : "memory");
        }
    }
}

extern "C" void kernel_launch(void* const* d_in, const int* in_sizes, int n_in,
                              void* d_out, int out_size) {
    const float* Q  = (const float*)d_in[0];
    const float* K  = (const float*)d_in[1];
    const float* V  = (const float*)d_in[2];
    const float* WQ = (const float*)d_in[3];
    const float* bQ = (const float*)d_in[4];
    const float* WK = (const float*)d_in[5];
    const float* bK = (const float*)d_in[6];

    prep_kernel<<<PGRID, 256>>>(Q, K, WQ, bQ, WK, bK, (float4*)d_out);
    wsum_kernel<<<PGRID, 256>>>(V, (float4*)d_out);
}